// round 4
// baseline (speedup 1.0000x reference)
#include <cuda_runtime.h>
#include <cuda_bf16.h>
#include <cstdint>

// ---------------------------------------------------------------------------
// GIN GraphEncoder: 3 layers of
//   agg = scatter_add(x[src] -> dst);  h = relu((x+agg)@W1[i]+b1[i]);  x = h@W2[i]+b2[i]
// then per-graph sum pool (batch is sorted).
//
// NOTE: reference uses jnp.int64 WITHOUT jax x64 enabled -> edge_index and
// batch are actually int32 on disk. We read them as int32.
// ---------------------------------------------------------------------------

static constexpr int N_NODES  = 100000;
static constexpr int N_EDGES  = 1600000;
static constexpr int D        = 128;
static constexpr int N_LAYERS = 3;
static constexpr int N_GRAPHS = 128;

// Scratch (alloc-free rule: __device__ globals), 16B-aligned for float4 paths.
__device__ __align__(16) float g_xcur[(size_t)N_NODES * D];
__device__ __align__(16) float g_agg [(size_t)N_NODES * D];
__device__ __align__(16) float g_h   [(size_t)N_NODES * D];

// ---------------------------------------------------------------------------
// copy / zero
// ---------------------------------------------------------------------------
__global__ void copy_kernel(const float* __restrict__ src, float* __restrict__ dst, int n4) {
    int i = blockIdx.x * blockDim.x + threadIdx.x;
    if (i < n4) {
        reinterpret_cast<float4*>(dst)[i] = reinterpret_cast<const float4*>(src)[i];
    }
}

__global__ void zero_kernel(float* __restrict__ dst, int n4) {
    int i = blockIdx.x * blockDim.x + threadIdx.x;
    if (i < n4) {
        reinterpret_cast<float4*>(dst)[i] = make_float4(0.f, 0.f, 0.f, 0.f);
    }
}

// ---------------------------------------------------------------------------
// Edge scatter-add: one warp per edge; lane handles one float4 (32*4 = 128)
// ---------------------------------------------------------------------------
__global__ void scatter_kernel(const float* __restrict__ x,
                               const int* __restrict__ ei,
                               float* __restrict__ agg) {
    int wid = (blockIdx.x * blockDim.x + threadIdx.x) >> 5;
    if (wid >= N_EDGES) return;
    int lane = threadIdx.x & 31;
    int s = ei[wid];            // src row
    int d = ei[N_EDGES + wid];  // dst row
    const float4 v = *reinterpret_cast<const float4*>(x + (size_t)s * D + lane * 4);
    float* p = agg + (size_t)d * D + lane * 4;
    asm volatile("red.global.add.v4.f32 [%0], {%1,%2,%3,%4};"
                 :: "l"(p), "f"(v.x), "f"(v.y), "f"(v.z), "f"(v.w)
                 : "memory");
}

// ---------------------------------------------------------------------------
// GEMM: C[M,128] = act(A[M,128] (+A2) @ W[128,128] + b)
// BM=64 rows per CTA, full 128 cols, BK=32. 256 threads, 8x4 micro-tile.
// ---------------------------------------------------------------------------
template <bool RELU, bool HAS_A2>
__global__ __launch_bounds__(256)
void gemm_kernel(const float* __restrict__ A, const float* __restrict__ A2,
                 const float* __restrict__ W, const float* __restrict__ bias,
                 float* __restrict__ C, int M) {
    constexpr int BM = 64;
    constexpr int BK = 32;
    __shared__ float sA[BM][BK + 1];
    __shared__ float sW[BK][D];

    const int row0 = blockIdx.x * BM;
    const int t    = threadIdx.x;
    const int cg   = t & 31;   // column group -> cols cg*4 .. cg*4+3
    const int rg   = t >> 5;   // row group    -> rows rg*8 .. rg*8+7

    float acc[8][4];
#pragma unroll
    for (int r = 0; r < 8; r++)
#pragma unroll
        for (int c = 0; c < 4; c++) acc[r][c] = 0.f;

    for (int k0 = 0; k0 < D; k0 += BK) {
        // Load A tile: 64 x 32 floats = 512 float4, 256 threads x 2
#pragma unroll
        for (int i = t; i < BM * (BK / 4); i += 256) {
            int r = i >> 3;
            int c = (i & 7) * 4;
            float4 v = make_float4(0.f, 0.f, 0.f, 0.f);
            int gr = row0 + r;
            if (gr < M) {
                v = *reinterpret_cast<const float4*>(A + (size_t)gr * D + k0 + c);
                if (HAS_A2) {
                    float4 u = *reinterpret_cast<const float4*>(A2 + (size_t)gr * D + k0 + c);
                    v.x += u.x; v.y += u.y; v.z += u.z; v.w += u.w;
                }
            }
            sA[r][c] = v.x; sA[r][c + 1] = v.y; sA[r][c + 2] = v.z; sA[r][c + 3] = v.w;
        }
        // Load W tile: 32 x 128 floats = 1024 float4, 256 threads x 4
#pragma unroll
        for (int i = t; i < BK * (D / 4); i += 256) {
            int r = i >> 5;
            int c = (i & 31) * 4;
            *reinterpret_cast<float4*>(&sW[r][c]) =
                *reinterpret_cast<const float4*>(W + (size_t)(k0 + r) * D + c);
        }
        __syncthreads();

#pragma unroll
        for (int kk = 0; kk < BK; kk++) {
            float4 wv = *reinterpret_cast<const float4*>(&sW[kk][cg * 4]);
            float a[8];
#pragma unroll
            for (int r = 0; r < 8; r++) a[r] = sA[rg * 8 + r][kk];
#pragma unroll
            for (int r = 0; r < 8; r++) {
                acc[r][0] += a[r] * wv.x;
                acc[r][1] += a[r] * wv.y;
                acc[r][2] += a[r] * wv.z;
                acc[r][3] += a[r] * wv.w;
            }
        }
        __syncthreads();
    }

    const float4 bv = *reinterpret_cast<const float4*>(&bias[cg * 4]);
#pragma unroll
    for (int r = 0; r < 8; r++) {
        int gr = row0 + rg * 8 + r;
        if (gr < M) {
            float4 o;
            o.x = acc[r][0] + bv.x;
            o.y = acc[r][1] + bv.y;
            o.z = acc[r][2] + bv.z;
            o.w = acc[r][3] + bv.w;
            if (RELU) {
                o.x = fmaxf(o.x, 0.f); o.y = fmaxf(o.y, 0.f);
                o.z = fmaxf(o.z, 0.f); o.w = fmaxf(o.w, 0.f);
            }
            *reinterpret_cast<float4*>(C + (size_t)gr * D + cg * 4) = o;
        }
    }
}

// ---------------------------------------------------------------------------
// Sum pool per graph. batch is sorted; one CTA per graph, one thread per dim.
// Deterministic (no atomics).
// ---------------------------------------------------------------------------
__device__ __forceinline__ int lower_bound_i(const int* a, int n, int key) {
    int lo = 0, hi = n;
    while (lo < hi) {
        int mid = (lo + hi) >> 1;
        if (a[mid] < key) lo = mid + 1; else hi = mid;
    }
    return lo;
}

__global__ void pool_kernel(const float* __restrict__ x,
                            const int* __restrict__ batch,
                            float* __restrict__ out) {
    int g = blockIdx.x;   // 0..127
    int d = threadIdx.x;  // 0..127
    int lo = lower_bound_i(batch, N_NODES, g);
    int hi = lower_bound_i(batch, N_NODES, g + 1);
    float s = 0.f;
    for (int r = lo; r < hi; r++) s += x[(size_t)r * D + d];
    out[g * D + d] = s;
}

// ---------------------------------------------------------------------------
// Launch. Inputs identified by element count (robust to metadata ordering):
//   x          : N_NODES*D      = 12,800,000
//   W1, W2     : N_LAYERS*D*D   = 49,152      (first seen = W1)
//   b1, b2     : N_LAYERS*D     = 384         (first seen = b1)
//   edge_index : 2*N_EDGES      = 3,200,000   (int32!)
//   batch      : N_NODES        = 100,000     (int32!)
// ---------------------------------------------------------------------------
extern "C" void kernel_launch(void* const* d_in, const int* in_sizes, int n_in,
                              void* d_out, int out_size) {
    const float *x_in = nullptr, *W1 = nullptr, *b1 = nullptr, *W2 = nullptr, *b2 = nullptr;
    const int *ei = nullptr, *batch = nullptr;

    for (int i = 0; i < n_in; i++) {
        int s = in_sizes[i];
        if (s == N_NODES * D)            x_in  = (const float*)d_in[i];
        else if (s == 2 * N_EDGES)       ei    = (const int*)d_in[i];
        else if (s == N_NODES)           batch = (const int*)d_in[i];
        else if (s == N_LAYERS * D * D) { if (!W1) W1 = (const float*)d_in[i]; else W2 = (const float*)d_in[i]; }
        else if (s == N_LAYERS * D)     { if (!b1) b1 = (const float*)d_in[i]; else b2 = (const float*)d_in[i]; }
    }
    float* out = (float*)d_out;

    float* xcur; cudaGetSymbolAddress((void**)&xcur, g_xcur);
    float* agg;  cudaGetSymbolAddress((void**)&agg,  g_agg);
    float* h;    cudaGetSymbolAddress((void**)&h,    g_h);

    const int n4 = N_NODES * D / 4;             // 3.2M float4
    const int feat_blocks = (n4 + 255) / 256;
    const int edge_blocks = (N_EDGES * 32 + 255) / 256;
    const int gemm_blocks = (N_NODES + 63) / 64;

    copy_kernel<<<feat_blocks, 256>>>(x_in, xcur, n4);

    for (int i = 0; i < N_LAYERS; i++) {
        zero_kernel<<<feat_blocks, 256>>>(agg, n4);
        scatter_kernel<<<edge_blocks, 256>>>(xcur, ei, agg);
        // h = relu((xcur + agg) @ W1[i] + b1[i])
        gemm_kernel<true, true><<<gemm_blocks, 256>>>(
            xcur, agg, W1 + (size_t)i * D * D, b1 + i * D, h, N_NODES);
        // xcur = h @ W2[i] + b2[i]
        gemm_kernel<false, false><<<gemm_blocks, 256>>>(
            h, nullptr, W2 + (size_t)i * D * D, b2 + i * D, xcur, N_NODES);
    }

    pool_kernel<<<N_GRAPHS, D>>>(xcur, batch, out);
}

// round 5
// speedup vs baseline: 1.8340x; 1.8340x over previous
#include <cuda_runtime.h>
#include <cuda_bf16.h>
#include <cstdint>

// ---------------------------------------------------------------------------
// GIN GraphEncoder, round 5:
//   - tf32 tensor-core GEMMs (mma.sync.m16n8k8)
//   - CSR build per call -> deterministic warp-per-node gather (no float REDs)
//   - parallel run-length pool
// edge_index / batch are int32 (jax default, x64 disabled).
// ---------------------------------------------------------------------------

static constexpr int N_NODES  = 100000;
static constexpr int N_EDGES  = 1600000;
static constexpr int D        = 128;
static constexpr int N_LAYERS = 3;
static constexpr int N_GRAPHS = 128;

// Scratch (__device__ globals per alloc-free rule)
__device__ __align__(16) float g_xcur[(size_t)N_NODES * D];
__device__ __align__(16) float g_agg [(size_t)N_NODES * D];
__device__ __align__(16) float g_h   [(size_t)N_NODES * D];
__device__ int g_counts  [N_NODES];
__device__ int g_rowstart[N_NODES + 1];
__device__ int g_cursor  [N_NODES];
__device__ int g_csr_src [N_EDGES];

// ---------------------------------------------------------------------------
// small utils
// ---------------------------------------------------------------------------
__global__ void copy_kernel(const float* __restrict__ src, float* __restrict__ dst, int n4) {
    int i = blockIdx.x * blockDim.x + threadIdx.x;
    if (i < n4) reinterpret_cast<float4*>(dst)[i] = reinterpret_cast<const float4*>(src)[i];
}

__global__ void zero_int_kernel(int* __restrict__ p, int n) {
    int i = blockIdx.x * blockDim.x + threadIdx.x;
    if (i < n) p[i] = 0;
}

__global__ void zero_float_kernel(float* __restrict__ p, int n) {
    int i = blockIdx.x * blockDim.x + threadIdx.x;
    if (i < n) p[i] = 0.f;
}

// ---------------------------------------------------------------------------
// CSR build: histogram -> scan -> fill
// ---------------------------------------------------------------------------
__global__ void hist_kernel(const int* __restrict__ ei, int* __restrict__ counts) {
    int e = blockIdx.x * blockDim.x + threadIdx.x;
    if (e < N_EDGES) atomicAdd(&counts[ei[N_EDGES + e]], 1);
}

// single-CTA hierarchical exclusive scan of counts -> rowstart (+ cursor copy)
__global__ void scan_kernel(const int* __restrict__ counts,
                            int* __restrict__ rowstart, int* __restrict__ cursor) {
    __shared__ int tsum[1024];
    const int t = threadIdx.x;
    const int CHUNK = (N_NODES + 1023) / 1024;  // 98
    const int lo = t * CHUNK;
    const int hi = min(lo + CHUNK, N_NODES);
    int s = 0;
    for (int i = lo; i < hi; i++) s += counts[i];
    tsum[t] = s;
    __syncthreads();
    // Hillis-Steele inclusive scan
    for (int st = 1; st < 1024; st <<= 1) {
        int v = (t >= st) ? tsum[t - st] : 0;
        __syncthreads();
        tsum[t] += v;
        __syncthreads();
    }
    int run = (t > 0) ? tsum[t - 1] : 0;  // exclusive prefix of this chunk
    for (int i = lo; i < hi; i++) {
        rowstart[i] = run;
        cursor[i]   = run;
        run += counts[i];
    }
    if (t == 0) rowstart[N_NODES] = N_EDGES;
}

__global__ void fill_kernel(const int* __restrict__ ei,
                            int* __restrict__ cursor, int* __restrict__ csr_src) {
    int e = blockIdx.x * blockDim.x + threadIdx.x;
    if (e < N_EDGES) {
        int s = ei[e];
        int d = ei[N_EDGES + e];
        int slot = atomicAdd(&cursor[d], 1);
        csr_src[slot] = s;
    }
}

// ---------------------------------------------------------------------------
// Gather: one warp per node; lane owns 4 dims (float4). Deterministic per dim.
// ---------------------------------------------------------------------------
__global__ void gather_kernel(const float* __restrict__ x,
                              const int* __restrict__ rowstart,
                              const int* __restrict__ csr_src,
                              float* __restrict__ agg) {
    int wid = (blockIdx.x * blockDim.x + threadIdx.x) >> 5;
    if (wid >= N_NODES) return;
    int lane = threadIdx.x & 31;
    int beg = rowstart[wid], end = rowstart[wid + 1];
    float4 acc = make_float4(0.f, 0.f, 0.f, 0.f);
    int i = beg;
    for (; i + 2 <= end; i += 2) {
        int s0 = csr_src[i], s1 = csr_src[i + 1];
        float4 v0 = *reinterpret_cast<const float4*>(x + (size_t)s0 * D + lane * 4);
        float4 v1 = *reinterpret_cast<const float4*>(x + (size_t)s1 * D + lane * 4);
        acc.x += v0.x + v1.x; acc.y += v0.y + v1.y;
        acc.z += v0.z + v1.z; acc.w += v0.w + v1.w;
    }
    if (i < end) {
        int s0 = csr_src[i];
        float4 v0 = *reinterpret_cast<const float4*>(x + (size_t)s0 * D + lane * 4);
        acc.x += v0.x; acc.y += v0.y; acc.z += v0.z; acc.w += v0.w;
    }
    *reinterpret_cast<float4*>(agg + (size_t)wid * D + lane * 4) = acc;
}

// ---------------------------------------------------------------------------
// tf32 tensor-core GEMM: C[M,128] = act((A (+A2)) @ W + b)
// CTA: 128 rows x 128 cols, 8 warps (4x2), warp tile 32x64, BK=32.
// ---------------------------------------------------------------------------
__device__ __forceinline__ uint32_t f2tf32(float f) {
    uint32_t r;
    asm("cvt.rna.tf32.f32 %0, %1;" : "=r"(r) : "f"(f));
    return r;
}

__device__ __forceinline__ void mma_tf32(float* c, const uint32_t* a, const uint32_t* b) {
    asm volatile(
        "mma.sync.aligned.m16n8k8.row.col.f32.tf32.tf32.f32 "
        "{%0,%1,%2,%3}, {%4,%5,%6,%7}, {%8,%9}, {%0,%1,%2,%3};"
        : "+f"(c[0]), "+f"(c[1]), "+f"(c[2]), "+f"(c[3])
        : "r"(a[0]), "r"(a[1]), "r"(a[2]), "r"(a[3]), "r"(b[0]), "r"(b[1]));
}

template <bool RELU, bool HAS_A2>
__global__ __launch_bounds__(256)
void gemm_tf32_kernel(const float* __restrict__ A, const float* __restrict__ A2,
                      const float* __restrict__ W, const float* __restrict__ bias,
                      float* __restrict__ C, int M) {
    constexpr int BM = 128;
    constexpr int BK = 32;
    constexpr int SA_LD = 36;   // (r*36 + c) % 32 conflict-free for fragment loads
    constexpr int SW_LD = 136;  // (k*136 + c) % 32 = k*8 + c -> conflict-free
    __shared__ uint32_t sA[BM * SA_LD];
    __shared__ uint32_t sW[BK * SW_LD];

    const int t      = threadIdx.x;
    const int warp   = t >> 5;
    const int lane   = t & 31;
    const int warp_m = warp & 3;       // 0..3 -> 32-row band
    const int warp_n = warp >> 2;      // 0..1 -> 64-col band
    const int row0   = blockIdx.x * BM;
    const int qr     = lane >> 2;      // 0..7
    const int qc     = lane & 3;       // 0..3

    float acc[2][8][4];
#pragma unroll
    for (int mt = 0; mt < 2; mt++)
#pragma unroll
        for (int nt = 0; nt < 8; nt++)
#pragma unroll
            for (int k = 0; k < 4; k++) acc[mt][nt][k] = 0.f;

    for (int k0 = 0; k0 < D; k0 += BK) {
        // A tile: 128 x 32 floats = 1024 float4 -> 4 iters/thread
#pragma unroll
        for (int i = t; i < BM * (BK / 4); i += 256) {
            int r = i >> 3;
            int c = (i & 7) * 4;
            float4 v = make_float4(0.f, 0.f, 0.f, 0.f);
            int gr = row0 + r;
            if (gr < M) {
                v = *reinterpret_cast<const float4*>(A + (size_t)gr * D + k0 + c);
                if (HAS_A2) {
                    float4 u = *reinterpret_cast<const float4*>(A2 + (size_t)gr * D + k0 + c);
                    v.x += u.x; v.y += u.y; v.z += u.z; v.w += u.w;
                }
            }
            uint32_t* p = &sA[r * SA_LD + c];
            p[0] = f2tf32(v.x); p[1] = f2tf32(v.y); p[2] = f2tf32(v.z); p[3] = f2tf32(v.w);
        }
        // W tile: 32 x 128 floats = 1024 float4 -> 4 iters/thread
#pragma unroll
        for (int i = t; i < BK * (D / 4); i += 256) {
            int r = i >> 5;
            int c = (i & 31) * 4;
            float4 v = *reinterpret_cast<const float4*>(W + (size_t)(k0 + r) * D + c);
            uint32_t* p = &sW[r * SW_LD + c];
            p[0] = f2tf32(v.x); p[1] = f2tf32(v.y); p[2] = f2tf32(v.z); p[3] = f2tf32(v.w);
        }
        __syncthreads();

#pragma unroll
        for (int ks = 0; ks < BK; ks += 8) {
            uint32_t af[2][4];
            uint32_t bf[8][2];
#pragma unroll
            for (int mt = 0; mt < 2; mt++) {
                int rb = warp_m * 32 + mt * 16;
                af[mt][0] = sA[(rb + qr)     * SA_LD + ks + qc];
                af[mt][1] = sA[(rb + qr + 8) * SA_LD + ks + qc];
                af[mt][2] = sA[(rb + qr)     * SA_LD + ks + qc + 4];
                af[mt][3] = sA[(rb + qr + 8) * SA_LD + ks + qc + 4];
            }
#pragma unroll
            for (int nt = 0; nt < 8; nt++) {
                int cb = warp_n * 64 + nt * 8 + qr;
                bf[nt][0] = sW[(ks + qc)     * SW_LD + cb];
                bf[nt][1] = sW[(ks + qc + 4) * SW_LD + cb];
            }
#pragma unroll
            for (int mt = 0; mt < 2; mt++)
#pragma unroll
                for (int nt = 0; nt < 8; nt++)
                    mma_tf32(acc[mt][nt], af[mt], bf[nt]);
        }
        __syncthreads();
    }

    // epilogue: bias (+relu), write float2 per fragment half
#pragma unroll
    for (int nt = 0; nt < 8; nt++) {
        int cb = warp_n * 64 + nt * 8 + 2 * qc;
        float bx = __ldg(&bias[cb]);
        float by = __ldg(&bias[cb + 1]);
#pragma unroll
        for (int mt = 0; mt < 2; mt++) {
            int r0 = row0 + warp_m * 32 + mt * 16 + qr;
            float2 v0, v1;
            v0.x = acc[mt][nt][0] + bx; v0.y = acc[mt][nt][1] + by;
            v1.x = acc[mt][nt][2] + bx; v1.y = acc[mt][nt][3] + by;
            if (RELU) {
                v0.x = fmaxf(v0.x, 0.f); v0.y = fmaxf(v0.y, 0.f);
                v1.x = fmaxf(v1.x, 0.f); v1.y = fmaxf(v1.y, 0.f);
            }
            if (r0 < M)     *reinterpret_cast<float2*>(C + (size_t)r0 * D + cb)       = v0;
            if (r0 + 8 < M) *reinterpret_cast<float2*>(C + (size_t)(r0 + 8) * D + cb) = v1;
        }
    }
}

// ---------------------------------------------------------------------------
// Pool: 400 CTAs x 128 threads; thread d run-length accumulates its dim over a
// 250-node chunk, atomicAdd flush on graph-id change (batch sorted).
// ---------------------------------------------------------------------------
__global__ void pool_kernel(const float* __restrict__ x,
                            const int* __restrict__ batch,
                            float* __restrict__ out) {
    constexpr int NCTA  = 400;
    constexpr int CHUNK = (N_NODES + NCTA - 1) / NCTA;  // 250
    int d  = threadIdx.x;
    int r0 = blockIdx.x * CHUNK;
    int r1 = min(r0 + CHUNK, N_NODES);
    if (r0 >= r1) return;
    int gcur = batch[r0];
    float s = 0.f;
    for (int r = r0; r < r1; r++) {
        int g = batch[r];
        if (g != gcur) {
            atomicAdd(&out[gcur * D + d], s);
            s = 0.f;
            gcur = g;
        }
        s += x[(size_t)r * D + d];
    }
    atomicAdd(&out[gcur * D + d], s);
}

// ---------------------------------------------------------------------------
// Launch. Inputs identified by element count:
//   x: 12,800,000 | edge_index: 3,200,000 (int32) | batch: 100,000 (int32)
//   W1/W2: 49,152 (first = W1) | b1/b2: 384 (first = b1)
// ---------------------------------------------------------------------------
extern "C" void kernel_launch(void* const* d_in, const int* in_sizes, int n_in,
                              void* d_out, int out_size) {
    const float *x_in = nullptr, *W1 = nullptr, *b1 = nullptr, *W2 = nullptr, *b2 = nullptr;
    const int *ei = nullptr, *batch = nullptr;

    for (int i = 0; i < n_in; i++) {
        int s = in_sizes[i];
        if (s == N_NODES * D)            x_in  = (const float*)d_in[i];
        else if (s == 2 * N_EDGES)       ei    = (const int*)d_in[i];
        else if (s == N_NODES)           batch = (const int*)d_in[i];
        else if (s == N_LAYERS * D * D) { if (!W1) W1 = (const float*)d_in[i]; else W2 = (const float*)d_in[i]; }
        else if (s == N_LAYERS * D)     { if (!b1) b1 = (const float*)d_in[i]; else b2 = (const float*)d_in[i]; }
    }
    float* out = (float*)d_out;

    float* xcur; cudaGetSymbolAddress((void**)&xcur, g_xcur);
    float* agg;  cudaGetSymbolAddress((void**)&agg,  g_agg);
    float* h;    cudaGetSymbolAddress((void**)&h,    g_h);
    int* counts;   cudaGetSymbolAddress((void**)&counts,   g_counts);
    int* rowstart; cudaGetSymbolAddress((void**)&rowstart, g_rowstart);
    int* cursor;   cudaGetSymbolAddress((void**)&cursor,   g_cursor);
    int* csr_src;  cudaGetSymbolAddress((void**)&csr_src,  g_csr_src);

    const int n4          = N_NODES * D / 4;
    const int feat_blocks = (n4 + 255) / 256;
    const int edge_blocks = (N_EDGES + 255) / 256;
    const int node_blocks = (N_NODES + 255) / 256;
    const int gemm_blocks = (N_NODES + 127) / 128;
    const int gat_blocks  = (N_NODES * 32 + 255) / 256;

    // CSR build (per call; deterministic structure)
    zero_int_kernel<<<node_blocks, 256>>>(counts, N_NODES);
    hist_kernel<<<edge_blocks, 256>>>(ei, counts);
    scan_kernel<<<1, 1024>>>(counts, rowstart, cursor);
    fill_kernel<<<edge_blocks, 256>>>(ei, cursor, csr_src);

    copy_kernel<<<feat_blocks, 256>>>(x_in, xcur, n4);

    for (int i = 0; i < N_LAYERS; i++) {
        gather_kernel<<<gat_blocks, 256>>>(xcur, rowstart, csr_src, agg);
        gemm_tf32_kernel<true, true><<<gemm_blocks, 256>>>(
            xcur, agg, W1 + (size_t)i * D * D, b1 + i * D, h, N_NODES);
        gemm_tf32_kernel<false, false><<<gemm_blocks, 256>>>(
            h, nullptr, W2 + (size_t)i * D * D, b2 + i * D, xcur, N_NODES);
    }

    zero_float_kernel<<<(N_GRAPHS * D + 255) / 256, 256>>>(out, N_GRAPHS * D);
    pool_kernel<<<400, 128>>>(xcur, batch, out);
}

// round 10
// speedup vs baseline: 1.9586x; 1.0679x over previous
#include <cuda_runtime.h>
#include <cuda_bf16.h>
#include <cstdint>

// ---------------------------------------------------------------------------
// GIN GraphEncoder, round 6:
//   - gather emits (x + agg) directly (GIN eps=0) -> single-input MLP
//   - fused 2-phase MLP kernel per layer: H=relu(A@W1+b1) staged in smem (tf32),
//     then C=H@W2+b2. No h round-trip through global.
//   - no input copy; layer 0 reads x_in in-place
// edge_index / batch are int32 (jax default, x64 disabled).
// ---------------------------------------------------------------------------

static constexpr int N_NODES  = 100000;
static constexpr int N_EDGES  = 1600000;
static constexpr int D        = 128;
static constexpr int N_LAYERS = 3;
static constexpr int N_GRAPHS = 128;

// Scratch (__device__ globals per alloc-free rule)
__device__ __align__(16) float g_xa  [(size_t)N_NODES * D];  // x + agg
__device__ __align__(16) float g_xcur[(size_t)N_NODES * D];  // layer output
__device__ int g_counts  [N_NODES];
__device__ int g_rowstart[N_NODES + 1];
__device__ int g_cursor  [N_NODES];
__device__ int g_csr_src [N_EDGES];

// ---------------------------------------------------------------------------
// CSR build: histogram -> scan -> fill
// ---------------------------------------------------------------------------
__global__ void hist_kernel(const int* __restrict__ ei, int* __restrict__ counts) {
    int e = blockIdx.x * blockDim.x + threadIdx.x;
    if (e < N_EDGES) atomicAdd(&counts[ei[N_EDGES + e]], 1);
}

// single-CTA hierarchical exclusive scan of counts -> rowstart (+ cursor copy)
__global__ void scan_kernel(const int* __restrict__ counts,
                            int* __restrict__ rowstart, int* __restrict__ cursor) {
    __shared__ int tsum[1024];
    const int t = threadIdx.x;
    const int CHUNK = (N_NODES + 1023) / 1024;  // 98
    const int lo = t * CHUNK;
    const int hi = min(lo + CHUNK, N_NODES);
    int s = 0;
    for (int i = lo; i < hi; i++) s += counts[i];
    tsum[t] = s;
    __syncthreads();
    for (int st = 1; st < 1024; st <<= 1) {
        int v = (t >= st) ? tsum[t - st] : 0;
        __syncthreads();
        tsum[t] += v;
        __syncthreads();
    }
    int run = (t > 0) ? tsum[t - 1] : 0;
    for (int i = lo; i < hi; i++) {
        rowstart[i] = run;
        cursor[i]   = run;
        run += counts[i];
    }
    if (t == 0) rowstart[N_NODES] = N_EDGES;
}

__global__ void fill_kernel(const int* __restrict__ ei,
                            int* __restrict__ cursor, int* __restrict__ csr_src) {
    int e = blockIdx.x * blockDim.x + threadIdx.x;
    if (e < N_EDGES) {
        int s = ei[e];
        int d = ei[N_EDGES + e];
        int slot = atomicAdd(&cursor[d], 1);
        csr_src[slot] = s;
    }
}

// ---------------------------------------------------------------------------
// Gather: one warp per node; lane owns 4 dims. Accumulator seeded with the
// node's own row (GIN: (1+eps)*x + agg, eps=0). Deterministic per dim.
// ---------------------------------------------------------------------------
__global__ void gather_kernel(const float* __restrict__ x,
                              const int* __restrict__ rowstart,
                              const int* __restrict__ csr_src,
                              float* __restrict__ xa) {
    int wid = (blockIdx.x * blockDim.x + threadIdx.x) >> 5;
    if (wid >= N_NODES) return;
    int lane = threadIdx.x & 31;
    int beg = rowstart[wid], end = rowstart[wid + 1];
    float4 acc = *reinterpret_cast<const float4*>(x + (size_t)wid * D + lane * 4);
    int i = beg;
    for (; i + 2 <= end; i += 2) {
        int s0 = csr_src[i], s1 = csr_src[i + 1];
        float4 v0 = *reinterpret_cast<const float4*>(x + (size_t)s0 * D + lane * 4);
        float4 v1 = *reinterpret_cast<const float4*>(x + (size_t)s1 * D + lane * 4);
        acc.x += v0.x + v1.x; acc.y += v0.y + v1.y;
        acc.z += v0.z + v1.z; acc.w += v0.w + v1.w;
    }
    if (i < end) {
        int s0 = csr_src[i];
        float4 v0 = *reinterpret_cast<const float4*>(x + (size_t)s0 * D + lane * 4);
        acc.x += v0.x; acc.y += v0.y; acc.z += v0.z; acc.w += v0.w;
    }
    *reinterpret_cast<float4*>(xa + (size_t)wid * D + lane * 4) = acc;
}

// ---------------------------------------------------------------------------
// Fused MLP: C = relu(A@W1+b1)@W2 + b2, tf32 tensor cores.
// CTA: 128 rows; 8 warps (4x2), warp tile 32x64, BK=32 chunks.
// H (128x128) staged in smem as tf32 between phases.
// ---------------------------------------------------------------------------
__device__ __forceinline__ uint32_t f2tf32(float f) {
    uint32_t r;
    asm("cvt.rna.tf32.f32 %0, %1;" : "=r"(r) : "f"(f));
    return r;
}

__device__ __forceinline__ void mma_tf32(float* c, const uint32_t* a, const uint32_t* b) {
    asm volatile(
        "mma.sync.aligned.m16n8k8.row.col.f32.tf32.tf32.f32 "
        "{%0,%1,%2,%3}, {%4,%5,%6,%7}, {%8,%9}, {%0,%1,%2,%3};"
        : "+f"(c[0]), "+f"(c[1]), "+f"(c[2]), "+f"(c[3])
        : "r"(a[0]), "r"(a[1]), "r"(a[2]), "r"(a[3]), "r"(b[0]), "r"(b[1]));
}

static constexpr int SA_LD = 36;    // (r*36+c)%32 conflict-free fragment loads
static constexpr int SW_LD = 136;   // (k*136+c)%32 = k*8+c -> conflict-free
static constexpr int SH_LD = 132;   // (r*132+c)%32 = r*4+c -> conflict-free
static constexpr int SA_WORDS = 128 * SA_LD;             // 4608
static constexpr int SW_WORDS = 32 * SW_LD;              // 4352
static constexpr int SH_WORDS = 128 * SH_LD;             // 16896
static constexpr int MLP_SMEM_BYTES = (SA_WORDS + SW_WORDS + SH_WORDS) * 4;  // 103424

__global__ __launch_bounds__(256)
void mlp_kernel(const float* __restrict__ A,
                const float* __restrict__ W1, const float* __restrict__ b1,
                const float* __restrict__ W2, const float* __restrict__ b2,
                float* __restrict__ C, int M) {
    extern __shared__ uint32_t smem[];
    uint32_t* sA = smem;
    uint32_t* sW = smem + SA_WORDS;
    uint32_t* sH = smem + SA_WORDS + SW_WORDS;

    constexpr int BM = 128;
    constexpr int BK = 32;

    const int t      = threadIdx.x;
    const int warp   = t >> 5;
    const int lane   = t & 31;
    const int warp_m = warp & 3;   // 32-row band
    const int warp_n = warp >> 2;  // 64-col band
    const int row0   = blockIdx.x * BM;
    const int qr     = lane >> 2;  // 0..7
    const int qc     = lane & 3;   // 0..3

    float acc[2][8][4];
#pragma unroll
    for (int mt = 0; mt < 2; mt++)
#pragma unroll
        for (int nt = 0; nt < 8; nt++)
#pragma unroll
            for (int k = 0; k < 4; k++) acc[mt][nt][k] = 0.f;

    // ---- phase 1: acc = A @ W1 ----
    for (int k0 = 0; k0 < D; k0 += BK) {
#pragma unroll
        for (int i = t; i < BM * (BK / 4); i += 256) {
            int r = i >> 3;
            int c = (i & 7) * 4;
            float4 v = make_float4(0.f, 0.f, 0.f, 0.f);
            int gr = row0 + r;
            if (gr < M) v = *reinterpret_cast<const float4*>(A + (size_t)gr * D + k0 + c);
            uint32_t* p = &sA[r * SA_LD + c];
            p[0] = f2tf32(v.x); p[1] = f2tf32(v.y); p[2] = f2tf32(v.z); p[3] = f2tf32(v.w);
        }
#pragma unroll
        for (int i = t; i < BK * (D / 4); i += 256) {
            int r = i >> 5;
            int c = (i & 31) * 4;
            float4 v = *reinterpret_cast<const float4*>(W1 + (size_t)(k0 + r) * D + c);
            uint32_t* p = &sW[r * SW_LD + c];
            p[0] = f2tf32(v.x); p[1] = f2tf32(v.y); p[2] = f2tf32(v.z); p[3] = f2tf32(v.w);
        }
        __syncthreads();

#pragma unroll
        for (int ks = 0; ks < BK; ks += 8) {
            uint32_t af[2][4], bf[8][2];
#pragma unroll
            for (int mt = 0; mt < 2; mt++) {
                int rb = warp_m * 32 + mt * 16;
                af[mt][0] = sA[(rb + qr)     * SA_LD + ks + qc];
                af[mt][1] = sA[(rb + qr + 8) * SA_LD + ks + qc];
                af[mt][2] = sA[(rb + qr)     * SA_LD + ks + qc + 4];
                af[mt][3] = sA[(rb + qr + 8) * SA_LD + ks + qc + 4];
            }
#pragma unroll
            for (int nt = 0; nt < 8; nt++) {
                int cb = warp_n * 64 + nt * 8 + qr;
                bf[nt][0] = sW[(ks + qc)     * SW_LD + cb];
                bf[nt][1] = sW[(ks + qc + 4) * SW_LD + cb];
            }
#pragma unroll
            for (int mt = 0; mt < 2; mt++)
#pragma unroll
                for (int nt = 0; nt < 8; nt++)
                    mma_tf32(acc[mt][nt], af[mt], bf[nt]);
        }
        __syncthreads();
    }

    // ---- H = relu(acc + b1) -> smem (tf32) ----
#pragma unroll
    for (int nt = 0; nt < 8; nt++) {
        int cb = warp_n * 64 + nt * 8 + 2 * qc;
        float bx = __ldg(&b1[cb]);
        float by = __ldg(&b1[cb + 1]);
#pragma unroll
        for (int mt = 0; mt < 2; mt++) {
            int r = warp_m * 32 + mt * 16 + qr;
            sH[r * SH_LD + cb]             = f2tf32(fmaxf(acc[mt][nt][0] + bx, 0.f));
            sH[r * SH_LD + cb + 1]         = f2tf32(fmaxf(acc[mt][nt][1] + by, 0.f));
            sH[(r + 8) * SH_LD + cb]       = f2tf32(fmaxf(acc[mt][nt][2] + bx, 0.f));
            sH[(r + 8) * SH_LD + cb + 1]   = f2tf32(fmaxf(acc[mt][nt][3] + by, 0.f));
        }
    }
    __syncthreads();

    // ---- phase 2: acc = H @ W2 ----
#pragma unroll
    for (int mt = 0; mt < 2; mt++)
#pragma unroll
        for (int nt = 0; nt < 8; nt++)
#pragma unroll
            for (int k = 0; k < 4; k++) acc[mt][nt][k] = 0.f;

    for (int k0 = 0; k0 < D; k0 += BK) {
#pragma unroll
        for (int i = t; i < BK * (D / 4); i += 256) {
            int r = i >> 5;
            int c = (i & 31) * 4;
            float4 v = *reinterpret_cast<const float4*>(W2 + (size_t)(k0 + r) * D + c);
            uint32_t* p = &sW[r * SW_LD + c];
            p[0] = f2tf32(v.x); p[1] = f2tf32(v.y); p[2] = f2tf32(v.z); p[3] = f2tf32(v.w);
        }
        __syncthreads();

#pragma unroll
        for (int ks = 0; ks < BK; ks += 8) {
            uint32_t af[2][4], bf[8][2];
#pragma unroll
            for (int mt = 0; mt < 2; mt++) {
                int rb = warp_m * 32 + mt * 16;
                af[mt][0] = sH[(rb + qr)     * SH_LD + k0 + ks + qc];
                af[mt][1] = sH[(rb + qr + 8) * SH_LD + k0 + ks + qc];
                af[mt][2] = sH[(rb + qr)     * SH_LD + k0 + ks + qc + 4];
                af[mt][3] = sH[(rb + qr + 8) * SH_LD + k0 + ks + qc + 4];
            }
#pragma unroll
            for (int nt = 0; nt < 8; nt++) {
                int cb = warp_n * 64 + nt * 8 + qr;
                bf[nt][0] = sW[(ks + qc)     * SW_LD + cb];
                bf[nt][1] = sW[(ks + qc + 4) * SW_LD + cb];
            }
#pragma unroll
            for (int mt = 0; mt < 2; mt++)
#pragma unroll
                for (int nt = 0; nt < 8; nt++)
                    mma_tf32(acc[mt][nt], af[mt], bf[nt]);
        }
        __syncthreads();
    }

    // ---- epilogue: C = acc + b2 ----
#pragma unroll
    for (int nt = 0; nt < 8; nt++) {
        int cb = warp_n * 64 + nt * 8 + 2 * qc;
        float bx = __ldg(&b2[cb]);
        float by = __ldg(&b2[cb + 1]);
#pragma unroll
        for (int mt = 0; mt < 2; mt++) {
            int r0 = row0 + warp_m * 32 + mt * 16 + qr;
            float2 v0, v1;
            v0.x = acc[mt][nt][0] + bx; v0.y = acc[mt][nt][1] + by;
            v1.x = acc[mt][nt][2] + bx; v1.y = acc[mt][nt][3] + by;
            if (r0 < M)     *reinterpret_cast<float2*>(C + (size_t)r0 * D + cb)       = v0;
            if (r0 + 8 < M) *reinterpret_cast<float2*>(C + (size_t)(r0 + 8) * D + cb) = v1;
        }
    }
}

// ---------------------------------------------------------------------------
// Pool: 400 CTAs x 128 threads; run-length accumulate per dim, atomic flush
// on graph-id change (batch sorted).
// ---------------------------------------------------------------------------
__global__ void pool_kernel(const float* __restrict__ x,
                            const int* __restrict__ batch,
                            float* __restrict__ out) {
    constexpr int NCTA  = 400;
    constexpr int CHUNK = (N_NODES + NCTA - 1) / NCTA;  // 250
    int d  = threadIdx.x;
    int r0 = blockIdx.x * CHUNK;
    int r1 = min(r0 + CHUNK, N_NODES);
    if (r0 >= r1) return;
    int gcur = batch[r0];
    float s = 0.f;
    for (int r = r0; r < r1; r++) {
        int g = batch[r];
        if (g != gcur) {
            atomicAdd(&out[gcur * D + d], s);
            s = 0.f;
            gcur = g;
        }
        s += x[(size_t)r * D + d];
    }
    atomicAdd(&out[gcur * D + d], s);
}

// ---------------------------------------------------------------------------
// Launch. Inputs identified by element count:
//   x: 12,800,000 | edge_index: 3,200,000 (int32) | batch: 100,000 (int32)
//   W1/W2: 49,152 (first = W1) | b1/b2: 384 (first = b1)
// ---------------------------------------------------------------------------
extern "C" void kernel_launch(void* const* d_in, const int* in_sizes, int n_in,
                              void* d_out, int out_size) {
    const float *x_in = nullptr, *W1 = nullptr, *b1 = nullptr, *W2 = nullptr, *b2 = nullptr;
    const int *ei = nullptr, *batch = nullptr;

    for (int i = 0; i < n_in; i++) {
        int s = in_sizes[i];
        if (s == N_NODES * D)            x_in  = (const float*)d_in[i];
        else if (s == 2 * N_EDGES)       ei    = (const int*)d_in[i];
        else if (s == N_NODES)           batch = (const int*)d_in[i];
        else if (s == N_LAYERS * D * D) { if (!W1) W1 = (const float*)d_in[i]; else W2 = (const float*)d_in[i]; }
        else if (s == N_LAYERS * D)     { if (!b1) b1 = (const float*)d_in[i]; else b2 = (const float*)d_in[i]; }
    }
    float* out = (float*)d_out;

    float* xa;   cudaGetSymbolAddress((void**)&xa,   g_xa);
    float* xcur; cudaGetSymbolAddress((void**)&xcur, g_xcur);
    int* counts;   cudaGetSymbolAddress((void**)&counts,   g_counts);
    int* rowstart; cudaGetSymbolAddress((void**)&rowstart, g_rowstart);
    int* cursor;   cudaGetSymbolAddress((void**)&cursor,   g_cursor);
    int* csr_src;  cudaGetSymbolAddress((void**)&csr_src,  g_csr_src);

    cudaFuncSetAttribute(mlp_kernel, cudaFuncAttributeMaxDynamicSharedMemorySize,
                         MLP_SMEM_BYTES);

    const int edge_blocks = (N_EDGES + 255) / 256;
    const int gemm_blocks = (N_NODES + 127) / 128;
    const int gat_blocks  = (N_NODES * 32 + 255) / 256;

    // CSR build (per call; deterministic structure)
    cudaMemsetAsync(counts, 0, N_NODES * sizeof(int));
    hist_kernel<<<edge_blocks, 256>>>(ei, counts);
    scan_kernel<<<1, 1024>>>(counts, rowstart, cursor);
    fill_kernel<<<edge_blocks, 256>>>(ei, cursor, csr_src);

    const float* xsrc = x_in;
    for (int i = 0; i < N_LAYERS; i++) {
        gather_kernel<<<gat_blocks, 256>>>(xsrc, rowstart, csr_src, xa);
        mlp_kernel<<<gemm_blocks, 256, MLP_SMEM_BYTES>>>(
            xa, W1 + (size_t)i * D * D, b1 + i * D,
            W2 + (size_t)i * D * D, b2 + i * D, xcur, N_NODES);
        xsrc = xcur;
    }

    cudaMemsetAsync(out, 0, (size_t)N_GRAPHS * D * sizeof(float));
    pool_kernel<<<400, 128>>>(xcur, batch, out);
}